// round 10
// baseline (speedup 1.0000x reference)
#include <cuda_runtime.h>
#include <math.h>

#define Bb 16
#define Tt 1000
#define IN_DIM 257
#define FEAT 771
#define HH 512
#define KN 9
#define M_ROWS (Bb*Tt)          // 16000
#define KPOOL (HH*KN)           // 4608

// ---------------- scratch (device globals; no alloc allowed) ----------------
__device__ float g_x0[Tt*Bb*HH];          // 32.8 MB  (T,B,H)
__device__ float g_x1[Tt*Bb*HH];          // 32.8 MB
__device__ float g_U [Tt*Bb*3*HH];        // 98.3 MB  (T,B,3H)
__device__ float g_pool[Bb*Tt*KPOOL];     // 294.9 MB (B,T,H*KN)

// ---------------- generic 128x128x16 SGEMM, 8x8 per thread ------------------
// Register-staged double buffering: prefetch K-tile k+1 into registers while
// computing tile k from smem, then commit regs->smem. Overlaps the ~250-580cy
// global latency with the ~512cy FFMA phase.
// A: (M,K) row-major. B: (K,N-view) with row stride ldb. Epilogue by MODE:
//  MODE 0: tanh(acc + bias[c]) -> write time-major C[(t*B+b)*H + c], r=b*T+t
//  MODE 1: plain C[r*N + c] = acc
//  MODE 2: sigmoid(acc + bias[c]) * extra[r*FEAT + IN_DIM + c] -> C[r*IN_DIM+c]
template<int MODE>
__global__ void gemm128(const float* __restrict__ A, const float* __restrict__ Bm,
                        float* __restrict__ C, int M, int N, int K, int ldb,
                        const float* __restrict__ bias,
                        const float* __restrict__ extra)
{
    const int BM = 128, BN = 128, BK = 16;
    __shared__ float As[BK][BM];
    __shared__ float Bs[BK][BN];

    const int tid  = threadIdx.x;            // 256 threads
    const int row0 = blockIdx.y * BM;
    const int col0 = blockIdx.x * BN;
    const int tr   = tid >> 4;               // 0..15
    const int tc   = tid & 15;               // 0..15

    // A tile loading: thread covers row a_r, 8 consecutive k
    const int a_r  = tid >> 1;               // 0..127
    const int a_k0 = (tid & 1) * 8;          // 0 or 8
    // B tile loading: thread covers row b_k, 8 consecutive n
    const int b_k  = tid >> 4;               // 0..15
    const int b_n0 = (tid & 15) * 8;         // 0..120

    const int gr_a = row0 + a_r;             // fixed A row for this thread

    float acc[8][8];
    #pragma unroll
    for (int i = 0; i < 8; i++)
        #pragma unroll
        for (int j = 0; j < 8; j++) acc[i][j] = 0.f;

    float pa[8], pb[8];                      // prefetch staging registers

    // ---- prologue: load K-tile 0 into staging regs ----
    {
        #pragma unroll
        for (int i = 0; i < 8; i++) {
            const int gk = a_k0 + i;
            pa[i] = (gr_a < M && gk < K) ? A[(long)gr_a * K + gk] : 0.f;
        }
        const int gk = b_k;
        #pragma unroll
        for (int j = 0; j < 8; j++) {
            const int gc = col0 + b_n0 + j;
            pb[j] = (gk < K && gc < N) ? Bm[(long)gk * ldb + gc] : 0.f;
        }
    }

    const int numK = (K + BK - 1) / BK;
    for (int kt = 0; kt < numK; kt++) {
        // commit staged tile kt to smem
        #pragma unroll
        for (int i = 0; i < 8; i++) As[a_k0 + i][a_r] = pa[i];
        #pragma unroll
        for (int j = 0; j < 8; j++) Bs[b_k][b_n0 + j] = pb[j];
        __syncthreads();

        // prefetch tile kt+1 into regs (batch-issued; overlaps compute below)
        if (kt + 1 < numK) {
            const int k0 = (kt + 1) * BK;
            #pragma unroll
            for (int i = 0; i < 8; i++) {
                const int gk = k0 + a_k0 + i;
                pa[i] = (gr_a < M && gk < K) ? A[(long)gr_a * K + gk] : 0.f;
            }
            const int gk = k0 + b_k;
            #pragma unroll
            for (int j = 0; j < 8; j++) {
                const int gc = col0 + b_n0 + j;
                pb[j] = (gk < K && gc < N) ? Bm[(long)gk * ldb + gc] : 0.f;
            }
        }

        // compute on smem tile kt
        #pragma unroll
        for (int kk = 0; kk < BK; kk++) {
            float ra[8], rb[8];
            #pragma unroll
            for (int i = 0; i < 8; i++) ra[i] = As[kk][tr * 8 + i];
            #pragma unroll
            for (int j = 0; j < 8; j++) rb[j] = Bs[kk][tc * 8 + j];
            #pragma unroll
            for (int i = 0; i < 8; i++)
                #pragma unroll
                for (int j = 0; j < 8; j++)
                    acc[i][j] = fmaf(ra[i], rb[j], acc[i][j]);
        }
        __syncthreads();
    }

    #pragma unroll
    for (int i = 0; i < 8; i++) {
        const int r = row0 + tr * 8 + i;
        if (r >= M) continue;
        #pragma unroll
        for (int j = 0; j < 8; j++) {
            const int c = col0 + tc * 8 + j;
            if (c >= N) continue;
            const float a = acc[i][j];
            if (MODE == 0) {
                const int b_ = r / Tt, t_ = r % Tt;
                C[((long)t_ * Bb + b_) * HH + c] = tanhf(a + bias[c]);
            } else if (MODE == 1) {
                C[(long)r * N + c] = a;
            } else {
                const float s = 1.f / (1.f + __expf(-(a + bias[c])));
                C[(long)r * IN_DIM + c] = s * extra[(long)r * FEAT + IN_DIM + c];
            }
        }
    }
}

// ---------------- SRU recurrent scan (1 thread per (b,h)) -------------------
// Only B*H = 8192 lanes exist (~1.7 warps/SM) -> no cross-warp latency hiding.
// Unroll t by 8 and batch all loads for the group so per-step cost approaches
// compute latency instead of serialized memory latency.
// (Recurrence is NOT parallelizable over t: f_t depends on c_{t-1} inside the
// sigmoid, so MLP batching is the only available lever.)
#define SRU_UNROLL 8
__global__ void __launch_bounds__(256)
sru_scan(const float* __restrict__ U,    // (T,B,3H)
         const float* __restrict__ xin,  // (T,B,H)
         float* __restrict__ hout,       // (T,B,H)
         const float* __restrict__ v,    // (2H)
         const float* __restrict__ bb)   // (2H)
{
    const int idx = blockIdx.x * blockDim.x + threadIdx.x;   // 0..B*H-1
    if (idx >= Bb * HH) return;
    const int b_ = idx / HH, h = idx % HH;
    const float vf = v[h], vr = v[HH + h];
    const float bf = bb[h], br = bb[HH + h];
    float c = 0.f;
    const float* Up = U    + (long)b_ * 3 * HH + h;
    const float* xp = xin  + (long)b_ * HH + h;
    float*       hp = hout + (long)b_ * HH + h;

    const int strideU = Bb * 3 * HH;
    const int strideX = Bb * HH;

    for (int t0 = 0; t0 < Tt; t0 += SRU_UNROLL) {
        float xt[SRU_UNROLL], fp[SRU_UNROLL], rp[SRU_UNROLL], xi[SRU_UNROLL];
        // batch-issue all loads for the group (high MLP, hides latency)
        #pragma unroll
        for (int u = 0; u < SRU_UNROLL; u++) {
            const float* Uq = Up + (long)u * strideU;
            xt[u] = __ldg(Uq);
            fp[u] = __ldg(Uq + HH);
            rp[u] = __ldg(Uq + 2 * HH);
            xi[u] = __ldg(xp + (long)u * strideX);
        }
        // sequential recurrence on registers
        #pragma unroll
        for (int u = 0; u < SRU_UNROLL; u++) {
            const float f  = 1.f / (1.f + __expf(-(fp[u] + vf * c + bf)));
            const float cn = f * c + (1.f - f) * xt[u];
            const float r  = 1.f / (1.f + __expf(-(rp[u] + vr * c + br)));
            hp[(long)u * strideX] = r * cn + (1.f - r) * xi[u];
            c = cn;
        }
        Up += (long)SRU_UNROLL * strideU;
        xp += (long)SRU_UNROLL * strideX;
        hp += (long)SRU_UNROLL * strideX;
    }
}

// ------- Fused Conv2d 6x6 (pad 3,2) + bias + tanh + MaxPool3x3(pad 1) -------
// Input: time-major (T,B,H), image (t,h) per batch. Output directly to
// g_pool (B,T,H*KN). Tile: 16(t) x 32(h) outputs per block.
//  - stage input patch 23x39 (zero-padded) in smem
//  - conv region 18x34 x 9 kernels -> smem, -INF outside image (matches
//    reduce_window(-inf) clipped pooling)
//  - 3x3 max from smem -> global
#define CT_T 16
#define CT_H 32
#define CV_T (CT_T + 2)            // 18
#define CV_H (CT_H + 2)            // 34
#define XS_T (CT_T + 7)            // 23
#define XS_H (CT_H + 7)            // 39
__global__ void __launch_bounds__(256)
conv_pool_fused(const float* __restrict__ x,
                const float* __restrict__ wk,  // (KN,1,6,6)
                const float* __restrict__ wb)  // (KN)
{
    __shared__ float w[KN * 36];
    __shared__ float bs[KN];
    __shared__ float Xs[XS_T][XS_H + 1];          // 23x40
    __shared__ float Ys[KN][CV_T][CV_H + 1];      // 9x18x35

    const int tid = threadIdx.x;                  // 256 threads
    for (int i = tid; i < KN * 36; i += 256) w[i] = wk[i];
    if (tid < KN) bs[tid] = wb[tid];

    const int b_ = blockIdx.z;
    const int t0 = blockIdx.y * CT_T;
    const int h0 = blockIdx.x * CT_H;

    // stage input patch: global (t0-4 + xi, h0-4 + xj), zero outside
    for (int i = tid; i < XS_T * XS_H; i += 256) {
        const int xi = i / XS_H, xj = i % XS_H;
        const int gt = t0 - 4 + xi;
        const int gh = h0 - 4 + xj;
        float val = 0.f;
        if (gt >= 0 && gt < Tt && gh >= 0 && gh < HH)
            val = x[((long)gt * Bb + b_) * HH + gh];
        Xs[xi][xj] = val;
    }
    __syncthreads();

    // conv 18x34 region: conv at global (t0-1+ci, h0-1+cj)
    for (int p = tid; p < CV_T * CV_H; p += 256) {
        const int ci = p / CV_H, cj = p % CV_H;
        const int ct = t0 - 1 + ci;
        const int ch = h0 - 1 + cj;
        const bool valid = (ct >= 0 && ct < Tt && ch >= 0 && ch < HH);

        float acc[KN];
        #pragma unroll
        for (int k = 0; k < KN; k++) acc[k] = 0.f;
        #pragma unroll
        for (int i = 0; i < 6; i++)
            #pragma unroll
            for (int j = 0; j < 6; j++) {
                const float val = Xs[ci + i][cj + j];
                #pragma unroll
                for (int k = 0; k < KN; k++)
                    acc[k] = fmaf(val, w[k * 36 + i * 6 + j], acc[k]);
            }
        #pragma unroll
        for (int k = 0; k < KN; k++)
            Ys[k][ci][cj] = valid ? tanhf(acc[k] + bs[k]) : -3.402823466e38f;
    }
    __syncthreads();

    // 3x3 max pool -> g_pool (B,T,H*KN)
    for (int p = tid; p < CT_T * CT_H; p += 256) {
        const int tt = p / CT_H, hh = p % CT_H;
        const int gt = t0 + tt;
        if (gt >= Tt) continue;
        const int gh = h0 + hh;
        float* outp = &g_pool[((long)b_ * Tt + gt) * KPOOL + gh * KN];
        #pragma unroll
        for (int k = 0; k < KN; k++) {
            float m = -3.402823466e38f;
            #pragma unroll
            for (int dt = 0; dt < 3; dt++)
                #pragma unroll
                for (int dh = 0; dh < 3; dh++)
                    m = fmaxf(m, Ys[k][tt + dt][hh + dh]);
            outp[k] = m;
        }
    }
}

// ---------------------------------------------------------------------------
extern "C" void kernel_launch(void* const* d_in, const int* in_sizes, int n_in,
                              void* d_out, int out_size)
{
    const float* inputs = (const float*)d_in[0];
    const float* W_in   = (const float*)d_in[1];
    const float* b_in   = (const float*)d_in[2];
    const float* W_rnn  = (const float*)d_in[3];   // (L,H,3H)
    const float* v_rnn  = (const float*)d_in[4];   // (L,2H)
    const float* b_rnn  = (const float*)d_in[5];   // (L,2H)
    const float* conv_k = (const float*)d_in[6];
    const float* conv_b = (const float*)d_in[7];
    const float* W_out  = (const float*)d_in[8];   // (H*KN, FEAT)
    const float* b_out  = (const float*)d_in[9];
    float* out = (float*)d_out;

    float *px0, *px1, *pU, *ppool;
    cudaGetSymbolAddress((void**)&px0,   g_x0);
    cudaGetSymbolAddress((void**)&px1,   g_x1);
    cudaGetSymbolAddress((void**)&pU,    g_U);
    cudaGetSymbolAddress((void**)&ppool, g_pool);

    const int mTiles = (M_ROWS + 127) / 128;   // 125

    // 1. input layer: tanh(inputs @ W_in + b_in), transposed to (T,B,H)
    gemm128<0><<<dim3((HH + 127) / 128, mTiles), 256>>>(
        inputs, W_in, px0, M_ROWS, HH, FEAT, HH, b_in, nullptr);

    // 2. SRU layers
    float* xin  = px0;
    float* xout = px1;
    for (int l = 0; l < 2; l++) {
        gemm128<1><<<dim3((3 * HH + 127) / 128, mTiles), 256>>>(
            xin, W_rnn + (long)l * HH * 3 * HH, pU,
            M_ROWS, 3 * HH, HH, 3 * HH, nullptr, nullptr);
        sru_scan<<<(Bb * HH + 255) / 256, 256>>>(
            pU, xin, xout, v_rnn + l * 2 * HH, b_rnn + l * 2 * HH);
        float* tmp = xin; xin = xout; xout = tmp;   // xin now holds layer output
    }
    // final hidden state is in `xin` (= px0 after 2 swaps)

    // 3+4. fused conv + tanh + maxpool -> (B,T,H*KN)
    conv_pool_fused<<<dim3(HH / CT_H, (Tt + CT_T - 1) / CT_T, Bb), 256>>>(
        xin, conv_k, conv_b);

    // 5. output: only columns [IN_DIM, 2*IN_DIM) of W_out are ever used
    gemm128<2><<<dim3((IN_DIM + 127) / 128, mTiles), 256>>>(
        ppool, W_out + IN_DIM, out, M_ROWS, IN_DIM, KPOOL, FEAT,
        b_out + IN_DIM, inputs);
}

// round 12
// speedup vs baseline: 1.6028x; 1.6028x over previous
#include <cuda_runtime.h>
#include <math.h>
#include <stdint.h>

#define Bb 16
#define Tt 1000
#define IN_DIM 257
#define FEAT 771
#define HH 512
#define KN 9
#define M_ROWS (Bb*Tt)          // 16000
#define KPOOL (HH*KN)           // 4608

// ---------------- scratch (device globals; no alloc allowed) ----------------
__device__ float g_x0[Tt*Bb*HH];          // 32.8 MB  (T,B,H)
__device__ float g_x1[Tt*Bb*HH];          // 32.8 MB
__device__ float g_U [Tt*Bb*3*HH];        // 98.3 MB  (T,B,3H)
__device__ float g_pool[Bb*Tt*KPOOL];     // 294.9 MB (B,T,H*KN)

__device__ __forceinline__ float to_tf32(float x) {
    uint32_t u;
    asm("cvt.rna.tf32.f32 %0, %1;" : "=r"(u) : "f"(x));
    return __uint_as_float(u);
}

// ------------- tf32 tensor-core GEMM: 128x128x16 tile, mma.m16n8k8 ----------
// Round-9 profile: FFMA SGEMM hit L1/smem crossbar roofline (L1=88.9%).
// mma.sync warp-tiles (64x32/warp) reuse fragments across the warp -> ~5x less
// smem traffic per FLOP. fp32 accumulate; inputs rounded to tf32 on smem store.
// 8 warps as 2(m) x 4(n). Per warp: 4 m-tiles(16) x 4 n-tiles(8), BK=16 = 2 k8.
// smem pad +8 words => all fragment LDS patterns bank-conflict-free.
// Epilogues identical to old gemm128 MODEs:
//  MODE 0: tanh(acc + bias[c]) -> time-major C[(t*B+b)*H + c], r=b*T+t
//  MODE 1: plain C[r*N + c] = acc
//  MODE 2: sigmoid(acc + bias[c]) * extra[r*FEAT + IN_DIM + c] -> C[r*IN_DIM+c]
template<int MODE>
__global__ void __launch_bounds__(256)
gemm_tf32(const float* __restrict__ A, const float* __restrict__ Bm,
          float* __restrict__ C, int M, int N, int K, int ldb,
          const float* __restrict__ bias, const float* __restrict__ extra)
{
    const int BM = 128, BN = 128, BK = 16;
    __shared__ float As[BK][BM + 8];
    __shared__ float Bs[BK][BN + 8];

    const int tid  = threadIdx.x;
    const int warp = tid >> 5, lane = tid & 31;
    const int grp  = lane >> 2, tg = lane & 3;
    const int wm   = (warp >> 2) * 64;      // 0 / 64
    const int wn   = (warp & 3) * 32;       // 0..96
    const int row0 = blockIdx.y * BM;
    const int col0 = blockIdx.x * BN;

    // A loader: thread row a_r, 8 consecutive k. B loader: column b_n, 8 k's.
    const int a_r = tid >> 1, a_k0 = (tid & 1) * 8;
    const int b_n = tid >> 1, b_k0 = (tid & 1) * 8;
    const int gr_a = row0 + a_r;
    const int gc_b = col0 + b_n;

    float acc[4][4][4];
    #pragma unroll
    for (int mi = 0; mi < 4; mi++)
        #pragma unroll
        for (int ni = 0; ni < 4; ni++)
            #pragma unroll
            for (int e = 0; e < 4; e++) acc[mi][ni][e] = 0.f;

    float pa[8], pb[8];
    // prologue: K-tile 0 into staging regs
    #pragma unroll
    for (int i = 0; i < 8; i++) {
        const int gk = a_k0 + i;
        pa[i] = (gr_a < M && gk < K) ? A[(long)gr_a * K + gk] : 0.f;
    }
    #pragma unroll
    for (int i = 0; i < 8; i++) {
        const int gk = b_k0 + i;
        pb[i] = (gk < K && gc_b < N) ? Bm[(long)gk * ldb + gc_b] : 0.f;
    }

    const int numK = (K + BK - 1) / BK;
    for (int kt = 0; kt < numK; kt++) {
        // commit staged tile (round inputs to tf32 here)
        #pragma unroll
        for (int i = 0; i < 8; i++) As[a_k0 + i][a_r] = to_tf32(pa[i]);
        #pragma unroll
        for (int i = 0; i < 8; i++) Bs[b_k0 + i][b_n] = to_tf32(pb[i]);
        __syncthreads();

        // prefetch next tile (overlaps tensor compute below)
        if (kt + 1 < numK) {
            const int k0 = (kt + 1) * BK;
            #pragma unroll
            for (int i = 0; i < 8; i++) {
                const int gk = k0 + a_k0 + i;
                pa[i] = (gr_a < M && gk < K) ? A[(long)gr_a * K + gk] : 0.f;
            }
            #pragma unroll
            for (int i = 0; i < 8; i++) {
                const int gk = k0 + b_k0 + i;
                pb[i] = (gk < K && gc_b < N) ? Bm[(long)gk * ldb + gc_b] : 0.f;
            }
        }

        // two k8 steps per K-tile
        #pragma unroll
        for (int s = 0; s < BK; s += 8) {
            uint32_t af[4][4], bf[4][2];
            #pragma unroll
            for (int mi = 0; mi < 4; mi++) {
                const int rm = wm + mi * 16 + grp;
                af[mi][0] = __float_as_uint(As[s + tg    ][rm    ]);
                af[mi][1] = __float_as_uint(As[s + tg    ][rm + 8]);
                af[mi][2] = __float_as_uint(As[s + tg + 4][rm    ]);
                af[mi][3] = __float_as_uint(As[s + tg + 4][rm + 8]);
            }
            #pragma unroll
            for (int ni = 0; ni < 4; ni++) {
                const int cn = wn + ni * 8 + grp;
                bf[ni][0] = __float_as_uint(Bs[s + tg    ][cn]);
                bf[ni][1] = __float_as_uint(Bs[s + tg + 4][cn]);
            }
            #pragma unroll
            for (int mi = 0; mi < 4; mi++)
                #pragma unroll
                for (int ni = 0; ni < 4; ni++) {
                    asm volatile(
                        "mma.sync.aligned.m16n8k8.row.col.f32.tf32.tf32.f32 "
                        "{%0,%1,%2,%3}, {%4,%5,%6,%7}, {%8,%9}, {%0,%1,%2,%3};\n"
                        : "+f"(acc[mi][ni][0]), "+f"(acc[mi][ni][1]),
                          "+f"(acc[mi][ni][2]), "+f"(acc[mi][ni][3])
                        : "r"(af[mi][0]), "r"(af[mi][1]),
                          "r"(af[mi][2]), "r"(af[mi][3]),
                          "r"(bf[ni][0]), "r"(bf[ni][1]));
                }
        }
        __syncthreads();
    }

    // epilogue: element e of (mi,ni): rows grp/grp+8, cols 2tg/2tg+1
    #pragma unroll
    for (int mi = 0; mi < 4; mi++) {
        #pragma unroll
        for (int ni = 0; ni < 4; ni++) {
            const int rg = row0 + wm + mi * 16 + grp;
            const int cg = col0 + wn + ni * 8 + 2 * tg;
            #pragma unroll
            for (int e = 0; e < 4; e++) {
                const int r = rg + (e >> 1) * 8;
                const int c = cg + (e & 1);
                if (r >= M || c >= N) continue;
                const float a = acc[mi][ni][e];
                if (MODE == 0) {
                    const int b_ = r / Tt, t_ = r % Tt;
                    C[((long)t_ * Bb + b_) * HH + c] = tanhf(a + bias[c]);
                } else if (MODE == 1) {
                    C[(long)r * N + c] = a;
                } else {
                    const float sg = 1.f / (1.f + __expf(-(a + bias[c])));
                    C[(long)r * IN_DIM + c] = sg * extra[(long)r * FEAT + IN_DIM + c];
                }
            }
        }
    }
}

// ---------------- SRU recurrent scan (1 thread per (b,h)) -------------------
// Recurrence not parallelizable over t (f_t needs c_{t-1} inside sigmoid);
// unroll-8 batches loads for MLP so per-step cost approaches compute latency.
#define SRU_UNROLL 8
__global__ void __launch_bounds__(256)
sru_scan(const float* __restrict__ U,    // (T,B,3H)
         const float* __restrict__ xin,  // (T,B,H)
         float* __restrict__ hout,       // (T,B,H)
         const float* __restrict__ v,    // (2H)
         const float* __restrict__ bb)   // (2H)
{
    const int idx = blockIdx.x * blockDim.x + threadIdx.x;   // 0..B*H-1
    if (idx >= Bb * HH) return;
    const int b_ = idx / HH, h = idx % HH;
    const float vf = v[h], vr = v[HH + h];
    const float bf = bb[h], br = bb[HH + h];
    float c = 0.f;
    const float* Up = U    + (long)b_ * 3 * HH + h;
    const float* xp = xin  + (long)b_ * HH + h;
    float*       hp = hout + (long)b_ * HH + h;

    const int strideU = Bb * 3 * HH;
    const int strideX = Bb * HH;

    for (int t0 = 0; t0 < Tt; t0 += SRU_UNROLL) {
        float xt[SRU_UNROLL], fp[SRU_UNROLL], rp[SRU_UNROLL], xi[SRU_UNROLL];
        #pragma unroll
        for (int u = 0; u < SRU_UNROLL; u++) {
            const float* Uq = Up + (long)u * strideU;
            xt[u] = __ldg(Uq);
            fp[u] = __ldg(Uq + HH);
            rp[u] = __ldg(Uq + 2 * HH);
            xi[u] = __ldg(xp + (long)u * strideX);
        }
        #pragma unroll
        for (int u = 0; u < SRU_UNROLL; u++) {
            const float f  = 1.f / (1.f + __expf(-(fp[u] + vf * c + bf)));
            const float cn = f * c + (1.f - f) * xt[u];
            const float r  = 1.f / (1.f + __expf(-(rp[u] + vr * c + br)));
            hp[(long)u * strideX] = r * cn + (1.f - r) * xi[u];
            c = cn;
        }
        Up += (long)SRU_UNROLL * strideU;
        xp += (long)SRU_UNROLL * strideX;
        hp += (long)SRU_UNROLL * strideX;
    }
}

// ------- Fused Conv2d 6x6 (pad 3,2) + bias + tanh + MaxPool3x3(pad 1) -------
#define CT_T 16
#define CT_H 32
#define CV_T (CT_T + 2)            // 18
#define CV_H (CT_H + 2)            // 34
#define XS_T (CT_T + 7)            // 23
#define XS_H (CT_H + 7)            // 39
__global__ void __launch_bounds__(256)
conv_pool_fused(const float* __restrict__ x,
                const float* __restrict__ wk,  // (KN,1,6,6)
                const float* __restrict__ wb)  // (KN)
{
    __shared__ float w[KN * 36];
    __shared__ float bs[KN];
    __shared__ float Xs[XS_T][XS_H + 1];          // 23x40
    __shared__ float Ys[KN][CV_T][CV_H + 1];      // 9x18x35

    const int tid = threadIdx.x;                  // 256 threads
    for (int i = tid; i < KN * 36; i += 256) w[i] = wk[i];
    if (tid < KN) bs[tid] = wb[tid];

    const int b_ = blockIdx.z;
    const int t0 = blockIdx.y * CT_T;
    const int h0 = blockIdx.x * CT_H;

    for (int i = tid; i < XS_T * XS_H; i += 256) {
        const int xi = i / XS_H, xj = i % XS_H;
        const int gt = t0 - 4 + xi;
        const int gh = h0 - 4 + xj;
        float val = 0.f;
        if (gt >= 0 && gt < Tt && gh >= 0 && gh < HH)
            val = x[((long)gt * Bb + b_) * HH + gh];
        Xs[xi][xj] = val;
    }
    __syncthreads();

    for (int p = tid; p < CV_T * CV_H; p += 256) {
        const int ci = p / CV_H, cj = p % CV_H;
        const int ct = t0 - 1 + ci;
        const int ch = h0 - 1 + cj;
        const bool valid = (ct >= 0 && ct < Tt && ch >= 0 && ch < HH);

        float acc[KN];
        #pragma unroll
        for (int k = 0; k < KN; k++) acc[k] = 0.f;
        #pragma unroll
        for (int i = 0; i < 6; i++)
            #pragma unroll
            for (int j = 0; j < 6; j++) {
                const float val = Xs[ci + i][cj + j];
                #pragma unroll
                for (int k = 0; k < KN; k++)
                    acc[k] = fmaf(val, w[k * 36 + i * 6 + j], acc[k]);
            }
        #pragma unroll
        for (int k = 0; k < KN; k++)
            Ys[k][ci][cj] = valid ? tanhf(acc[k] + bs[k]) : -3.402823466e38f;
    }
    __syncthreads();

    for (int p = tid; p < CT_T * CT_H; p += 256) {
        const int tt = p / CT_H, hh = p % CT_H;
        const int gt = t0 + tt;
        if (gt >= Tt) continue;
        const int gh = h0 + hh;
        float* outp = &g_pool[((long)b_ * Tt + gt) * KPOOL + gh * KN];
        #pragma unroll
        for (int k = 0; k < KN; k++) {
            float m = -3.402823466e38f;
            #pragma unroll
            for (int dt = 0; dt < 3; dt++)
                #pragma unroll
                for (int dh = 0; dh < 3; dh++)
                    m = fmaxf(m, Ys[k][tt + dt][hh + dh]);
            outp[k] = m;
        }
    }
}

// ---------------------------------------------------------------------------
extern "C" void kernel_launch(void* const* d_in, const int* in_sizes, int n_in,
                              void* d_out, int out_size)
{
    const float* inputs = (const float*)d_in[0];
    const float* W_in   = (const float*)d_in[1];
    const float* b_in   = (const float*)d_in[2];
    const float* W_rnn  = (const float*)d_in[3];   // (L,H,3H)
    const float* v_rnn  = (const float*)d_in[4];   // (L,2H)
    const float* b_rnn  = (const float*)d_in[5];   // (L,2H)
    const float* conv_k = (const float*)d_in[6];
    const float* conv_b = (const float*)d_in[7];
    const float* W_out  = (const float*)d_in[8];   // (H*KN, FEAT)
    const float* b_out  = (const float*)d_in[9];
    float* out = (float*)d_out;

    float *px0, *px1, *pU, *ppool;
    cudaGetSymbolAddress((void**)&px0,   g_x0);
    cudaGetSymbolAddress((void**)&px1,   g_x1);
    cudaGetSymbolAddress((void**)&pU,    g_U);
    cudaGetSymbolAddress((void**)&ppool, g_pool);

    const int mTiles = (M_ROWS + 127) / 128;   // 125

    // 1. input layer: tanh(inputs @ W_in + b_in), transposed to (T,B,H)
    gemm_tf32<0><<<dim3((HH + 127) / 128, mTiles), 256>>>(
        inputs, W_in, px0, M_ROWS, HH, FEAT, HH, b_in, nullptr);

    // 2. SRU layers
    float* xin  = px0;
    float* xout = px1;
    for (int l = 0; l < 2; l++) {
        gemm_tf32<1><<<dim3((3 * HH + 127) / 128, mTiles), 256>>>(
            xin, W_rnn + (long)l * HH * 3 * HH, pU,
            M_ROWS, 3 * HH, HH, 3 * HH, nullptr, nullptr);
        sru_scan<<<(Bb * HH + 255) / 256, 256>>>(
            pU, xin, xout, v_rnn + l * 2 * HH, b_rnn + l * 2 * HH);
        float* tmp = xin; xin = xout; xout = tmp;   // xin now holds layer output
    }
    // final hidden state is in `xin` (= px0 after 2 swaps)

    // 3+4. fused conv + tanh + maxpool -> (B,T,H*KN)
    conv_pool_fused<<<dim3(HH / CT_H, (Tt + CT_T - 1) / CT_T, Bb), 256>>>(
        xin, conv_k, conv_b);

    // 5. output: only columns [IN_DIM, 2*IN_DIM) of W_out are ever used
    gemm_tf32<2><<<dim3((IN_DIM + 127) / 128, mTiles), 256>>>(
        ppool, W_out + IN_DIM, out, M_ROWS, IN_DIM, KPOOL, FEAT,
        b_out + IN_DIM, inputs);
}

// round 13
// speedup vs baseline: 1.6728x; 1.0437x over previous
#include <cuda_runtime.h>
#include <math.h>
#include <stdint.h>

#define Bb 16
#define Tt 1000
#define IN_DIM 257
#define FEAT 771
#define HH 512
#define KN 9
#define M_ROWS (Bb*Tt)          // 16000
#define KPOOL (HH*KN)           // 4608

// ---------------- scratch (device globals; no alloc allowed) ----------------
__device__ float g_x0[Tt*Bb*HH];          // 32.8 MB  (T,B,H)
__device__ float g_x1[Tt*Bb*HH];          // 32.8 MB
__device__ float g_U [Tt*Bb*3*HH];        // 98.3 MB  (T,B,3H)
__device__ float g_pool[Bb*Tt*KPOOL];     // 294.9 MB (B,T,H*KN)

__device__ __forceinline__ float to_tf32(float x) {
    uint32_t u;
    asm("cvt.rna.tf32.f32 %0, %1;" : "=r"(u) : "f"(x));
    return __uint_as_float(u);
}

// ------------- tf32 tensor-core GEMM: 128x128x16 tile, mma.m16n8k8 ----------
// R12 profile: tensor=20.8%, L1=79.6%, issue=28.9% -> latency-bound; store+
// double-barrier per K-tile on critical path. This version:
//  - 2-stage smem double buffer: compute buf while staging kt+1; store into
//    buf^1 after compute; ONE barrier per tile.
//  - nvalid[] warp-uniform guard: skip MMAs/B-frags for column tiles beyond N
//    (kills the ~97%-dead third col-tile of the N=257 output GEMM).
// 8 warps 2(m)x4(n); per warp 64x32 = 4x4 m16n8k8 tiles; BK=16 = 2 k8 steps.
//  MODE 0: tanh(acc + bias[c]) -> time-major C[(t*B+b)*H + c], r=b*T+t
//  MODE 1: plain C[r*N + c] = acc
//  MODE 2: sigmoid(acc + bias[c]) * extra[r*FEAT + IN_DIM + c] -> C[r*IN_DIM+c]
template<int MODE>
__global__ void __launch_bounds__(256)
gemm_tf32(const float* __restrict__ A, const float* __restrict__ Bm,
          float* __restrict__ C, int M, int N, int K, int ldb,
          const float* __restrict__ bias, const float* __restrict__ extra)
{
    const int BM = 128, BN = 128, BK = 16;
    __shared__ float As[2][BK][BM + 8];
    __shared__ float Bs[2][BK][BN + 8];

    const int tid  = threadIdx.x;
    const int warp = tid >> 5, lane = tid & 31;
    const int grp  = lane >> 2, tg = lane & 3;
    const int wm   = (warp >> 2) * 64;      // 0 / 64
    const int wn   = (warp & 3) * 32;       // 0..96
    const int row0 = blockIdx.y * BM;
    const int col0 = blockIdx.x * BN;

    const int a_r = tid >> 1, a_k0 = (tid & 1) * 8;
    const int b_n = tid >> 1, b_k0 = (tid & 1) * 8;
    const int gr_a = row0 + a_r;
    const int gc_b = col0 + b_n;

    // warp-uniform column-tile validity (skip dead MMA work in N-tail blocks)
    bool nvalid[4];
    #pragma unroll
    for (int ni = 0; ni < 4; ni++) nvalid[ni] = (col0 + wn + ni * 8) < N;

    float acc[4][4][4];
    #pragma unroll
    for (int mi = 0; mi < 4; mi++)
        #pragma unroll
        for (int ni = 0; ni < 4; ni++)
            #pragma unroll
            for (int e = 0; e < 4; e++) acc[mi][ni][e] = 0.f;

    float pa[8], pb[8];
    // prologue: tile 0 -> regs -> smem buf 0
    #pragma unroll
    for (int i = 0; i < 8; i++) {
        const int gk = a_k0 + i;
        pa[i] = (gr_a < M && gk < K) ? A[(long)gr_a * K + gk] : 0.f;
    }
    #pragma unroll
    for (int i = 0; i < 8; i++) {
        const int gk = b_k0 + i;
        pb[i] = (gk < K && gc_b < N) ? Bm[(long)gk * ldb + gc_b] : 0.f;
    }
    #pragma unroll
    for (int i = 0; i < 8; i++) As[0][a_k0 + i][a_r] = to_tf32(pa[i]);
    #pragma unroll
    for (int i = 0; i < 8; i++) Bs[0][b_k0 + i][b_n] = to_tf32(pb[i]);
    __syncthreads();

    const int numK = (K + BK - 1) / BK;
    for (int kt = 0; kt < numK; kt++) {
        const int buf = kt & 1;
        const bool more = (kt + 1 < numK);

        // stage next tile into regs (global latency hidden by compute below)
        if (more) {
            const int k0 = (kt + 1) * BK;
            #pragma unroll
            for (int i = 0; i < 8; i++) {
                const int gk = k0 + a_k0 + i;
                pa[i] = (gr_a < M && gk < K) ? A[(long)gr_a * K + gk] : 0.f;
            }
            #pragma unroll
            for (int i = 0; i < 8; i++) {
                const int gk = k0 + b_k0 + i;
                pb[i] = (gk < K && gc_b < N) ? Bm[(long)gk * ldb + gc_b] : 0.f;
            }
        }

        // compute on buf
        #pragma unroll
        for (int s = 0; s < BK; s += 8) {
            uint32_t af[4][4], bf[4][2];
            #pragma unroll
            for (int mi = 0; mi < 4; mi++) {
                const int rm = wm + mi * 16 + grp;
                af[mi][0] = __float_as_uint(As[buf][s + tg    ][rm    ]);
                af[mi][1] = __float_as_uint(As[buf][s + tg    ][rm + 8]);
                af[mi][2] = __float_as_uint(As[buf][s + tg + 4][rm    ]);
                af[mi][3] = __float_as_uint(As[buf][s + tg + 4][rm + 8]);
            }
            #pragma unroll
            for (int ni = 0; ni < 4; ni++) {
                if (!nvalid[ni]) continue;
                const int cn = wn + ni * 8 + grp;
                bf[ni][0] = __float_as_uint(Bs[buf][s + tg    ][cn]);
                bf[ni][1] = __float_as_uint(Bs[buf][s + tg + 4][cn]);
            }
            #pragma unroll
            for (int mi = 0; mi < 4; mi++)
                #pragma unroll
                for (int ni = 0; ni < 4; ni++) {
                    if (!nvalid[ni]) continue;
                    asm volatile(
                        "mma.sync.aligned.m16n8k8.row.col.f32.tf32.tf32.f32 "
                        "{%0,%1,%2,%3}, {%4,%5,%6,%7}, {%8,%9}, {%0,%1,%2,%3};\n"
                        : "+f"(acc[mi][ni][0]), "+f"(acc[mi][ni][1]),
                          "+f"(acc[mi][ni][2]), "+f"(acc[mi][ni][3])
                        : "r"(af[mi][0]), "r"(af[mi][1]),
                          "r"(af[mi][2]), "r"(af[mi][3]),
                          "r"(bf[ni][0]), "r"(bf[ni][1]));
                }
        }

        // commit staged tile into the other buffer (read of it finished at
        // the barrier that ended iteration kt-1)
        if (more) {
            #pragma unroll
            for (int i = 0; i < 8; i++) As[buf ^ 1][a_k0 + i][a_r] = to_tf32(pa[i]);
            #pragma unroll
            for (int i = 0; i < 8; i++) Bs[buf ^ 1][b_k0 + i][b_n] = to_tf32(pb[i]);
        }
        __syncthreads();
    }

    // epilogue: element e of (mi,ni): rows grp/grp+8, cols 2tg/2tg+1
    #pragma unroll
    for (int mi = 0; mi < 4; mi++) {
        #pragma unroll
        for (int ni = 0; ni < 4; ni++) {
            if (!nvalid[ni]) continue;
            const int rg = row0 + wm + mi * 16 + grp;
            const int cg = col0 + wn + ni * 8 + 2 * tg;
            #pragma unroll
            for (int e = 0; e < 4; e++) {
                const int r = rg + (e >> 1) * 8;
                const int c = cg + (e & 1);
                if (r >= M || c >= N) continue;
                const float a = acc[mi][ni][e];
                if (MODE == 0) {
                    const int b_ = r / Tt, t_ = r % Tt;
                    C[((long)t_ * Bb + b_) * HH + c] = tanhf(a + bias[c]);
                } else if (MODE == 1) {
                    C[(long)r * N + c] = a;
                } else {
                    const float sg = 1.f / (1.f + __expf(-(a + bias[c])));
                    C[(long)r * IN_DIM + c] = sg * extra[(long)r * FEAT + IN_DIM + c];
                }
            }
        }
    }
}

// ---------------- SRU recurrent scan (1 thread per (b,h)) -------------------
#define SRU_UNROLL 8
__global__ void __launch_bounds__(256)
sru_scan(const float* __restrict__ U,    // (T,B,3H)
         const float* __restrict__ xin,  // (T,B,H)
         float* __restrict__ hout,       // (T,B,H)
         const float* __restrict__ v,    // (2H)
         const float* __restrict__ bb)   // (2H)
{
    const int idx = blockIdx.x * blockDim.x + threadIdx.x;   // 0..B*H-1
    if (idx >= Bb * HH) return;
    const int b_ = idx / HH, h = idx % HH;
    const float vf = v[h], vr = v[HH + h];
    const float bf = bb[h], br = bb[HH + h];
    float c = 0.f;
    const float* Up = U    + (long)b_ * 3 * HH + h;
    const float* xp = xin  + (long)b_ * HH + h;
    float*       hp = hout + (long)b_ * HH + h;

    const int strideU = Bb * 3 * HH;
    const int strideX = Bb * HH;

    for (int t0 = 0; t0 < Tt; t0 += SRU_UNROLL) {
        float xt[SRU_UNROLL], fp[SRU_UNROLL], rp[SRU_UNROLL], xi[SRU_UNROLL];
        #pragma unroll
        for (int u = 0; u < SRU_UNROLL; u++) {
            const float* Uq = Up + (long)u * strideU;
            xt[u] = __ldg(Uq);
            fp[u] = __ldg(Uq + HH);
            rp[u] = __ldg(Uq + 2 * HH);
            xi[u] = __ldg(xp + (long)u * strideX);
        }
        #pragma unroll
        for (int u = 0; u < SRU_UNROLL; u++) {
            const float f  = 1.f / (1.f + __expf(-(fp[u] + vf * c + bf)));
            const float cn = f * c + (1.f - f) * xt[u];
            const float r  = 1.f / (1.f + __expf(-(rp[u] + vr * c + br)));
            hp[(long)u * strideX] = r * cn + (1.f - r) * xi[u];
            c = cn;
        }
        Up += (long)SRU_UNROLL * strideU;
        xp += (long)SRU_UNROLL * strideX;
        hp += (long)SRU_UNROLL * strideX;
    }
}

// ------- Fused Conv2d 6x6 (pad 3,2) + bias + tanh + MaxPool3x3(pad 1) -------
#define CT_T 16
#define CT_H 32
#define CV_T (CT_T + 2)            // 18
#define CV_H (CT_H + 2)            // 34
#define XS_T (CT_T + 7)            // 23
#define XS_H (CT_H + 7)            // 39
__global__ void __launch_bounds__(256)
conv_pool_fused(const float* __restrict__ x,
                const float* __restrict__ wk,  // (KN,1,6,6)
                const float* __restrict__ wb)  // (KN)
{
    __shared__ float w[KN * 36];
    __shared__ float bs[KN];
    __shared__ float Xs[XS_T][XS_H + 1];          // 23x40
    __shared__ float Ys[KN][CV_T][CV_H + 1];      // 9x18x35

    const int tid = threadIdx.x;                  // 256 threads
    for (int i = tid; i < KN * 36; i += 256) w[i] = wk[i];
    if (tid < KN) bs[tid] = wb[tid];

    const int b_ = blockIdx.z;
    const int t0 = blockIdx.y * CT_T;
    const int h0 = blockIdx.x * CT_H;

    for (int i = tid; i < XS_T * XS_H; i += 256) {
        const int xi = i / XS_H, xj = i % XS_H;
        const int gt = t0 - 4 + xi;
        const int gh = h0 - 4 + xj;
        float val = 0.f;
        if (gt >= 0 && gt < Tt && gh >= 0 && gh < HH)
            val = x[((long)gt * Bb + b_) * HH + gh];
        Xs[xi][xj] = val;
    }
    __syncthreads();

    for (int p = tid; p < CV_T * CV_H; p += 256) {
        const int ci = p / CV_H, cj = p % CV_H;
        const int ct = t0 - 1 + ci;
        const int ch = h0 - 1 + cj;
        const bool valid = (ct >= 0 && ct < Tt && ch >= 0 && ch < HH);

        float acc[KN];
        #pragma unroll
        for (int k = 0; k < KN; k++) acc[k] = 0.f;
        #pragma unroll
        for (int i = 0; i < 6; i++)
            #pragma unroll
            for (int j = 0; j < 6; j++) {
                const float val = Xs[ci + i][cj + j];
                #pragma unroll
                for (int k = 0; k < KN; k++)
                    acc[k] = fmaf(val, w[k * 36 + i * 6 + j], acc[k]);
            }
        #pragma unroll
        for (int k = 0; k < KN; k++)
            Ys[k][ci][cj] = valid ? tanhf(acc[k] + bs[k]) : -3.402823466e38f;
    }
    __syncthreads();

    for (int p = tid; p < CT_T * CT_H; p += 256) {
        const int tt = p / CT_H, hh = p % CT_H;
        const int gt = t0 + tt;
        if (gt >= Tt) continue;
        const int gh = h0 + hh;
        float* outp = &g_pool[((long)b_ * Tt + gt) * KPOOL + gh * KN];
        #pragma unroll
        for (int k = 0; k < KN; k++) {
            float m = -3.402823466e38f;
            #pragma unroll
            for (int dt = 0; dt < 3; dt++)
                #pragma unroll
                for (int dh = 0; dh < 3; dh++)
                    m = fmaxf(m, Ys[k][tt + dt][hh + dh]);
            outp[k] = m;
        }
    }
}

// ---------------------------------------------------------------------------
extern "C" void kernel_launch(void* const* d_in, const int* in_sizes, int n_in,
                              void* d_out, int out_size)
{
    const float* inputs = (const float*)d_in[0];
    const float* W_in   = (const float*)d_in[1];
    const float* b_in   = (const float*)d_in[2];
    const float* W_rnn  = (const float*)d_in[3];   // (L,H,3H)
    const float* v_rnn  = (const float*)d_in[4];   // (L,2H)
    const float* b_rnn  = (const float*)d_in[5];   // (L,2H)
    const float* conv_k = (const float*)d_in[6];
    const float* conv_b = (const float*)d_in[7];
    const float* W_out  = (const float*)d_in[8];   // (H*KN, FEAT)
    const float* b_out  = (const float*)d_in[9];
    float* out = (float*)d_out;

    float *px0, *px1, *pU, *ppool;
    cudaGetSymbolAddress((void**)&px0,   g_x0);
    cudaGetSymbolAddress((void**)&px1,   g_x1);
    cudaGetSymbolAddress((void**)&pU,    g_U);
    cudaGetSymbolAddress((void**)&ppool, g_pool);

    const int mTiles = (M_ROWS + 127) / 128;   // 125

    // 1. input layer: tanh(inputs @ W_in + b_in), transposed to (T,B,H)
    gemm_tf32<0><<<dim3((HH + 127) / 128, mTiles), 256>>>(
        inputs, W_in, px0, M_ROWS, HH, FEAT, HH, b_in, nullptr);

    // 2. SRU layers
    float* xin  = px0;
    float* xout = px1;
    for (int l = 0; l < 2; l++) {
        gemm_tf32<1><<<dim3((3 * HH + 127) / 128, mTiles), 256>>>(
            xin, W_rnn + (long)l * HH * 3 * HH, pU,
            M_ROWS, 3 * HH, HH, 3 * HH, nullptr, nullptr);
        sru_scan<<<(Bb * HH + 255) / 256, 256>>>(
            pU, xin, xout, v_rnn + l * 2 * HH, b_rnn + l * 2 * HH);
        float* tmp = xin; xin = xout; xout = tmp;   // xin now holds layer output
    }
    // final hidden state is in `xin` (= px0 after 2 swaps)

    // 3+4. fused conv + tanh + maxpool -> (B,T,H*KN)
    conv_pool_fused<<<dim3(HH / CT_H, (Tt + CT_T - 1) / CT_T, Bb), 256>>>(
        xin, conv_k, conv_b);

    // 5. output: only columns [IN_DIM, 2*IN_DIM) of W_out are ever used
    gemm_tf32<2><<<dim3((IN_DIM + 127) / 128, mTiles), 256>>>(
        ppool, W_out + IN_DIM, out, M_ROWS, IN_DIM, KPOOL, FEAT,
        b_out + IN_DIM, inputs);
}